// round 14
// baseline (speedup 1.0000x reference)
#include <cuda_runtime.h>
#include <stdint.h>

// out[b] = sum_{s=0}^{199} w_weight[text[s,b]] + bias
// text (200, 2048) row-major, tokens in [0, 50000)
//
// Converged design (R9, best measured 5.50us kernel / 6.62us total):
//  - 64 CTAs x 1024 threads, single wave, 1 CTA/SM (204KB smem)
//  - full 200KB fp32 weight table staged in smem via two 100KB
//    cp.async.bulk chunks, each with its own mbarrier
//  - coalesced (S,B)-layout index loads front-batched under the TMA stream
//  - runtime int32/int64 dtype detection via odd-word vote (tokens < 50000)
//  - gather pass A (vocab < 25000) overlaps chunk 1's stream; pass B after
//  - conflict-free smem tree reduce, 32-thread epilogue adds bias
#define S_TOK 200
#define B_PHR 2048
#define V_SZ  50000
#define V_HALF 25000
#define HALF_BYTES (V_HALF * 4)         // 100000 B (16B multiple)
#define PHR_PER_BLK 32
#define NBLK (B_PHR / PHR_PER_BLK)      // 64 blocks
#define NTHR 1024
#define NGRP 32
#define RED_FLOATS (NGRP * PHR_PER_BLK) // 1024
#define SMEM_BYTES (V_SZ * 4 + RED_FLOATS * 4 + 2 * 8 + 8)

__device__ __forceinline__ uint32_t smem_u32(const void* p) {
    uint32_t a;
    asm("{ .reg .u64 t; cvta.to.shared.u64 t, %1; cvt.u32.u64 %0, t; }"
        : "=r"(a) : "l"(p));
    return a;
}

__device__ __forceinline__ void mbar_wait0(uint32_t mbar_a) {
    uint32_t done;
    asm volatile(
        "{\n\t.reg .pred P;\n\t"
        "mbarrier.try_wait.parity.acquire.cta.shared::cta.b64 P, [%1], 0;\n\t"
        "selp.b32 %0, 1, 0, P;\n\t}"
        : "=r"(done) : "r"(mbar_a) : "memory");
    if (!done) {
        asm volatile(
            "{\n\t.reg .pred P;\n\t"
            "WL_%=:\n\t"
            "mbarrier.try_wait.parity.acquire.cta.shared::cta.b64 P, [%0], 0, 0x989680;\n\t"
            "@P bra.uni WD_%=;\n\t"
            "bra.uni WL_%=;\n\t"
            "WD_%=:\n\t}"
            :: "r"(mbar_a) : "memory");
    }
}

__global__ __launch_bounds__(NTHR, 1) void MNB_455266533601_kernel(
    const void* __restrict__ text_raw,
    const float* __restrict__ w_weight,
    const float* __restrict__ w_bias,
    float* __restrict__ out)
{
    extern __shared__ float smem[];
    float* sw  = smem;                     // [V_SZ] staged table
    float* red = smem + V_SZ;              // [NGRP][PHR_PER_BLK]
    unsigned long long* mbar =
        (unsigned long long*)(smem + V_SZ + RED_FLOATS);   // [2]

    const int tid = threadIdx.x;
    const int p   = tid & (PHR_PER_BLK - 1);   // phrase within block
    const int g   = tid >> 5;                  // s-group
    const int b   = blockIdx.x * PHR_PER_BLK + p;
    const uint32_t mbar0_a = smem_u32(mbar);

    // ---- init both mbarriers, one sync, then issue both TMA chunks ----
    if (tid == 0) {
        asm volatile("mbarrier.init.shared.b64 [%0], 1;" :: "r"(mbar0_a) : "memory");
        asm volatile("mbarrier.init.shared.b64 [%0], 1;" :: "r"(mbar0_a + 8) : "memory");
    }
    __syncthreads();   // init visible to all waiters

    if (tid == 0) {
        uint32_t dst = smem_u32(sw);
        const char* src = (const char*)w_weight;
#pragma unroll
        for (int c = 0; c < 2; c++) {
            asm volatile("mbarrier.arrive.expect_tx.shared.b64 _, [%0], %1;"
                         :: "r"(mbar0_a + 8 * c), "r"((uint32_t)HALF_BYTES) : "memory");
            asm volatile(
                "cp.async.bulk.shared::cta.global.mbarrier::complete_tx::bytes "
                "[%0], [%1], %2, [%3];"
                :: "r"(dst + c * HALF_BYTES), "l"(src + (size_t)c * HALF_BYTES),
                   "r"((uint32_t)HALF_BYTES), "r"(mbar0_a + 8 * c)
                : "memory");
        }
    }

    // ---- dtype detection: int64 buffers have zero odd 32-bit words ----
    const unsigned int* __restrict__ t32 = (const unsigned int*)text_raw;
    unsigned int probe = t32[2 * (tid & 31) + 1];
    const bool is64 = __all_sync(0xffffffffu, probe == 0u);

    // s-groups 0..7 take 7 tokens, 8..31 take 6  (8*7 + 24*6 = 200)
    const int cnt = (g < 8) ? 7 : 6;
    const int s0  = (g < 8) ? g * 7 : 56 + (g - 8) * 6;

    // ---- front-batched coalesced index loads (overlap the TMA stream) ----
    int idx[7];
    if (is64) {
        const long long* __restrict__ t = (const long long*)text_raw;
#pragma unroll
        for (int i = 0; i < 7; i++)
            if (i < cnt) idx[i] = (int)t[(size_t)(s0 + i) * B_PHR + b];
    } else {
        const int* __restrict__ t = (const int*)text_raw;
#pragma unroll
        for (int i = 0; i < 7; i++)
            if (i < cnt) idx[i] = t[(s0 + i) * B_PHR + b];
    }

    // ---- pass A: lower vocab half, while the upper half is still streaming ----
    float acc = 0.0f;
    mbar_wait0(mbar0_a);
#pragma unroll
    for (int i = 0; i < 7; i++)
        if (i < cnt && idx[i] < V_HALF) acc += sw[idx[i]];

    // ---- pass B: upper half ----
    mbar_wait0(mbar0_a + 8);
#pragma unroll
    for (int i = 0; i < 7; i++)
        if (i < cnt && idx[i] >= V_HALF) acc += sw[idx[i]];

    // ---- reduce 32 partials per phrase ----
    red[g * PHR_PER_BLK + p] = acc;
    __syncthreads();

    if (tid < PHR_PER_BLK) {
        float sum = 0.0f;
#pragma unroll
        for (int j = 0; j < NGRP; j++) sum += red[j * PHR_PER_BLK + tid];
        out[blockIdx.x * PHR_PER_BLK + tid] = sum + __ldg(w_bias);
    }
}

extern "C" void kernel_launch(void* const* d_in, const int* in_sizes, int n_in,
                              void* d_out, int out_size) {
    const void*  text   = d_in[0];                 // (200, 2048) int32 or int64
    const float* weight = (const float*)d_in[1];   // (1, 50000) float32
    const float* bias   = (const float*)d_in[2];   // (1,) float32
    float*       out    = (float*)d_out;           // (2048, 1) float32

    cudaFuncSetAttribute(MNB_455266533601_kernel,
                         cudaFuncAttributeMaxDynamicSharedMemorySize, SMEM_BYTES);
    cudaFuncSetAttribute(MNB_455266533601_kernel,
                         cudaFuncAttributePreferredSharedMemoryCarveout,
                         cudaSharedmemCarveoutMaxShared);

    MNB_455266533601_kernel<<<NBLK, NTHR, SMEM_BYTES>>>(text, weight, bias, out);
}

// round 15
// speedup vs baseline: 1.0417x; 1.0417x over previous
#include <cuda_runtime.h>
#include <stdint.h>

// out[b] = sum_{s=0}^{199} w_weight[text[s,b]] + bias
// text (200, 2048) row-major, tokens in [0, 50000)
//
// Converged design (best measured: 5.54us kernel / 6.62us total, reproduced):
//  - 64 CTAs x 1024 threads, single wave, 1 CTA/SM (204KB smem)
//  - full 200KB fp32 weight table staged in smem via two 100KB
//    cp.async.bulk chunks, each with its own mbarrier
//  - coalesced (S,B)-layout index loads front-batched under the TMA stream
//  - runtime int32/int64 dtype detection via odd-word vote (tokens < 50000)
//  - bias pre-loaded before the waits (hidden); gather pass A (vocab < 25000)
//    overlaps chunk 1's stream; pass B after; smem tree reduce epilogue
#define S_TOK 200
#define B_PHR 2048
#define V_SZ  50000
#define V_HALF 25000
#define HALF_BYTES (V_HALF * 4)         // 100000 B (16B multiple)
#define PHR_PER_BLK 32
#define NBLK (B_PHR / PHR_PER_BLK)      // 64 blocks
#define NTHR 1024
#define NGRP 32
#define RED_FLOATS (NGRP * PHR_PER_BLK) // 1024
#define SMEM_BYTES (V_SZ * 4 + RED_FLOATS * 4 + 2 * 8 + 8)

__device__ __forceinline__ uint32_t smem_u32(const void* p) {
    uint32_t a;
    asm("{ .reg .u64 t; cvta.to.shared.u64 t, %1; cvt.u32.u64 %0, t; }"
        : "=r"(a) : "l"(p));
    return a;
}

__device__ __forceinline__ void mbar_wait0(uint32_t mbar_a) {
    uint32_t done;
    asm volatile(
        "{\n\t.reg .pred P;\n\t"
        "mbarrier.try_wait.parity.acquire.cta.shared::cta.b64 P, [%1], 0;\n\t"
        "selp.b32 %0, 1, 0, P;\n\t}"
        : "=r"(done) : "r"(mbar_a) : "memory");
    if (!done) {
        asm volatile(
            "{\n\t.reg .pred P;\n\t"
            "WL_%=:\n\t"
            "mbarrier.try_wait.parity.acquire.cta.shared::cta.b64 P, [%0], 0, 0x989680;\n\t"
            "@P bra.uni WD_%=;\n\t"
            "bra.uni WL_%=;\n\t"
            "WD_%=:\n\t}"
            :: "r"(mbar_a) : "memory");
    }
}

__global__ __launch_bounds__(NTHR, 1) void MNB_455266533601_kernel(
    const void* __restrict__ text_raw,
    const float* __restrict__ w_weight,
    const float* __restrict__ w_bias,
    float* __restrict__ out)
{
    extern __shared__ float smem[];
    float* sw  = smem;                     // [V_SZ] staged table
    float* red = smem + V_SZ;              // [NGRP][PHR_PER_BLK]
    unsigned long long* mbar =
        (unsigned long long*)(smem + V_SZ + RED_FLOATS);   // [2]

    const int tid = threadIdx.x;
    const int p   = tid & (PHR_PER_BLK - 1);   // phrase within block
    const int g   = tid >> 5;                  // s-group
    const int b   = blockIdx.x * PHR_PER_BLK + p;
    const uint32_t mbar0_a = smem_u32(mbar);

    // ---- init both mbarriers, one sync, then issue both TMA chunks ----
    if (tid == 0) {
        asm volatile("mbarrier.init.shared.b64 [%0], 1;" :: "r"(mbar0_a) : "memory");
        asm volatile("mbarrier.init.shared.b64 [%0], 1;" :: "r"(mbar0_a + 8) : "memory");
    }
    __syncthreads();   // init visible to all waiters

    if (tid == 0) {
        uint32_t dst = smem_u32(sw);
        const char* src = (const char*)w_weight;
#pragma unroll
        for (int c = 0; c < 2; c++) {
            asm volatile("mbarrier.arrive.expect_tx.shared.b64 _, [%0], %1;"
                         :: "r"(mbar0_a + 8 * c), "r"((uint32_t)HALF_BYTES) : "memory");
            asm volatile(
                "cp.async.bulk.shared::cta.global.mbarrier::complete_tx::bytes "
                "[%0], [%1], %2, [%3];"
                :: "r"(dst + c * HALF_BYTES), "l"(src + (size_t)c * HALF_BYTES),
                   "r"((uint32_t)HALF_BYTES), "r"(mbar0_a + 8 * c)
                : "memory");
        }
    }

    // ---- dtype detection: int64 buffers have zero odd 32-bit words ----
    const unsigned int* __restrict__ t32 = (const unsigned int*)text_raw;
    unsigned int probe = t32[2 * (tid & 31) + 1];
    const bool is64 = __all_sync(0xffffffffu, probe == 0u);

    // s-groups 0..7 take 7 tokens, 8..31 take 6  (8*7 + 24*6 = 200)
    const int cnt = (g < 8) ? 7 : 6;
    const int s0  = (g < 8) ? g * 7 : 56 + (g - 8) * 6;

    // ---- front-batched coalesced index loads (overlap the TMA stream) ----
    int idx[7];
    if (is64) {
        const long long* __restrict__ t = (const long long*)text_raw;
#pragma unroll
        for (int i = 0; i < 7; i++)
            if (i < cnt) idx[i] = (int)t[(size_t)(s0 + i) * B_PHR + b];
    } else {
        const int* __restrict__ t = (const int*)text_raw;
#pragma unroll
        for (int i = 0; i < 7; i++)
            if (i < cnt) idx[i] = t[(s0 + i) * B_PHR + b];
    }

    // bias pre-loaded here: its latency hides under the mbarrier wait below
    const float bias = __ldg(w_bias);

    // ---- pass A: lower vocab half, while the upper half is still streaming ----
    float acc = 0.0f;
    mbar_wait0(mbar0_a);
#pragma unroll
    for (int i = 0; i < 7; i++)
        if (i < cnt && idx[i] < V_HALF) acc += sw[idx[i]];

    // ---- pass B: upper half ----
    mbar_wait0(mbar0_a + 8);
#pragma unroll
    for (int i = 0; i < 7; i++)
        if (i < cnt && idx[i] >= V_HALF) acc += sw[idx[i]];

    // ---- reduce 32 partials per phrase ----
    red[g * PHR_PER_BLK + p] = acc;
    __syncthreads();

    if (tid < PHR_PER_BLK) {
        float sum = 0.0f;
#pragma unroll
        for (int j = 0; j < NGRP; j++) sum += red[j * PHR_PER_BLK + tid];
        out[blockIdx.x * PHR_PER_BLK + tid] = sum + bias;
    }
}

extern "C" void kernel_launch(void* const* d_in, const int* in_sizes, int n_in,
                              void* d_out, int out_size) {
    const void*  text   = d_in[0];                 // (200, 2048) int32 or int64
    const float* weight = (const float*)d_in[1];   // (1, 50000) float32
    const float* bias   = (const float*)d_in[2];   // (1,) float32
    float*       out    = (float*)d_out;           // (2048, 1) float32

    cudaFuncSetAttribute(MNB_455266533601_kernel,
                         cudaFuncAttributeMaxDynamicSharedMemorySize, SMEM_BYTES);
    cudaFuncSetAttribute(MNB_455266533601_kernel,
                         cudaFuncAttributePreferredSharedMemoryCarveout,
                         cudaSharedmemCarveoutMaxShared);

    MNB_455266533601_kernel<<<NBLK, NTHR, SMEM_BYTES>>>(text, weight, bias, out);
}

// round 17
// speedup vs baseline: 1.0870x; 1.0435x over previous
#include <cuda_runtime.h>
#include <stdint.h>

// out[b] = sum_{s=0}^{199} w_weight[text[s,b]] + bias
// text (200, 2048) row-major, tokens in [0, 50000)
//
// R9 converged design, block-size probe: 512 threads (16 warps) per CTA.
//  - 64 CTAs, single wave, 1 CTA/SM (full-table 200KB smem staging)
//  - two 100KB cp.async.bulk chunks, per-chunk mbarriers
//  - pass A (vocab < 25000) overlaps chunk 1's stream; pass B after
#define S_TOK 200
#define B_PHR 2048
#define V_SZ  50000
#define V_HALF 25000
#define HALF_BYTES (V_HALF * 4)         // 100000 B (16B multiple)
#define PHR_PER_BLK 32
#define NBLK (B_PHR / PHR_PER_BLK)      // 64 blocks
#define NTHR 512
#define NGRP 16                          // s-groups per phrase (512/32)
#define RED_FLOATS (NGRP * PHR_PER_BLK) // 512
#define SMEM_BYTES (V_SZ * 4 + RED_FLOATS * 4 + 2 * 8 + 8)

__device__ __forceinline__ uint32_t smem_u32(const void* p) {
    uint32_t a;
    asm("{ .reg .u64 t; cvta.to.shared.u64 t, %1; cvt.u32.u64 %0, t; }"
        : "=r"(a) : "l"(p));
    return a;
}

__device__ __forceinline__ void mbar_wait0(uint32_t mbar_a) {
    uint32_t done;
    asm volatile(
        "{\n\t.reg .pred P;\n\t"
        "mbarrier.try_wait.parity.acquire.cta.shared::cta.b64 P, [%1], 0;\n\t"
        "selp.b32 %0, 1, 0, P;\n\t}"
        : "=r"(done) : "r"(mbar_a) : "memory");
    if (!done) {
        asm volatile(
            "{\n\t.reg .pred P;\n\t"
            "WL_%=:\n\t"
            "mbarrier.try_wait.parity.acquire.cta.shared::cta.b64 P, [%0], 0, 0x989680;\n\t"
            "@P bra.uni WD_%=;\n\t"
            "bra.uni WL_%=;\n\t"
            "WD_%=:\n\t}"
            :: "r"(mbar_a) : "memory");
    }
}

__global__ __launch_bounds__(NTHR, 1) void MNB_455266533601_kernel(
    const void* __restrict__ text_raw,
    const float* __restrict__ w_weight,
    const float* __restrict__ w_bias,
    float* __restrict__ out)
{
    extern __shared__ float smem[];
    float* sw  = smem;                     // [V_SZ] staged table
    float* red = smem + V_SZ;              // [NGRP][PHR_PER_BLK]
    unsigned long long* mbar =
        (unsigned long long*)(smem + V_SZ + RED_FLOATS);   // [2]

    const int tid = threadIdx.x;
    const int p   = tid & (PHR_PER_BLK - 1);   // phrase within block
    const int g   = tid >> 5;                  // s-group (0..15)
    const int b   = blockIdx.x * PHR_PER_BLK + p;
    const uint32_t mbar0_a = smem_u32(mbar);

    // ---- init both mbarriers, one sync, then issue both TMA chunks ----
    if (tid == 0) {
        asm volatile("mbarrier.init.shared.b64 [%0], 1;" :: "r"(mbar0_a) : "memory");
        asm volatile("mbarrier.init.shared.b64 [%0], 1;" :: "r"(mbar0_a + 8) : "memory");
    }
    __syncthreads();   // init visible to all waiters

    if (tid == 0) {
        uint32_t dst = smem_u32(sw);
        const char* src = (const char*)w_weight;
#pragma unroll
        for (int c = 0; c < 2; c++) {
            asm volatile("mbarrier.arrive.expect_tx.shared.b64 _, [%0], %1;"
                         :: "r"(mbar0_a + 8 * c), "r"((uint32_t)HALF_BYTES) : "memory");
            asm volatile(
                "cp.async.bulk.shared::cta.global.mbarrier::complete_tx::bytes "
                "[%0], [%1], %2, [%3];"
                :: "r"(dst + c * HALF_BYTES), "l"(src + (size_t)c * HALF_BYTES),
                   "r"((uint32_t)HALF_BYTES), "r"(mbar0_a + 8 * c)
                : "memory");
        }
    }

    // ---- dtype detection: int64 buffers have zero odd 32-bit words ----
    const unsigned int* __restrict__ t32 = (const unsigned int*)text_raw;
    unsigned int probe = t32[2 * (tid & 31) + 1];
    const bool is64 = __all_sync(0xffffffffu, probe == 0u);

    // s-groups 0..7 take 13 tokens, 8..15 take 12  (8*13 + 8*12 = 200)
    const int cnt = (g < 8) ? 13 : 12;
    const int s0  = (g < 8) ? g * 13 : 104 + (g - 8) * 12;

    // ---- front-batched coalesced index loads (overlap the TMA stream) ----
    int idx[13];
    if (is64) {
        const long long* __restrict__ t = (const long long*)text_raw;
#pragma unroll
        for (int i = 0; i < 13; i++)
            if (i < cnt) idx[i] = (int)t[(size_t)(s0 + i) * B_PHR + b];
    } else {
        const int* __restrict__ t = (const int*)text_raw;
#pragma unroll
        for (int i = 0; i < 13; i++)
            if (i < cnt) idx[i] = t[(s0 + i) * B_PHR + b];
    }

    // bias pre-loaded: latency hides under the mbarrier wait below
    const float bias = __ldg(w_bias);

    // ---- pass A: lower vocab half, while the upper half is still streaming ----
    float acc = 0.0f;
    mbar_wait0(mbar0_a);
#pragma unroll
    for (int i = 0; i < 13; i++)
        if (i < cnt && idx[i] < V_HALF) acc += sw[idx[i]];

    // ---- pass B: upper half ----
    mbar_wait0(mbar0_a + 8);
#pragma unroll
    for (int i = 0; i < 13; i++)
        if (i < cnt && idx[i] >= V_HALF) acc += sw[idx[i]];

    // ---- reduce 16 partials per phrase ----
    red[g * PHR_PER_BLK + p] = acc;
    __syncthreads();

    if (tid < PHR_PER_BLK) {
        float sum = 0.0f;
#pragma unroll
        for (int j = 0; j < NGRP; j++) sum += red[j * PHR_PER_BLK + tid];
        out[blockIdx.x * PHR_PER_BLK + tid] = sum + bias;
    }
}

extern "C" void kernel_launch(void* const* d_in, const int* in_sizes, int n_in,
                              void* d_out, int out_size) {
    const void*  text   = d_in[0];                 // (200, 2048) int32 or int64
    const float* weight = (const float*)d_in[1];   // (1, 50000) float32
    const float* bias   = (const float*)d_in[2];   // (1,) float32
    float*       out    = (float*)d_out;           // (2048, 1) float32

    cudaFuncSetAttribute(MNB_455266533601_kernel,
                         cudaFuncAttributeMaxDynamicSharedMemorySize, SMEM_BYTES);
    cudaFuncSetAttribute(MNB_455266533601_kernel,
                         cudaFuncAttributePreferredSharedMemoryCarveout,
                         cudaSharedmemCarveoutMaxShared);

    MNB_455266533601_kernel<<<NBLK, NTHR, SMEM_BYTES>>>(text, weight, bias, out);
}